// round 15
// baseline (speedup 1.0000x reference)
#include <cuda_runtime.h>
#include <cstdint>

#define TT 512
#define BB 1024
#define VV 64
#define HH 100
#define H3 300
#define ROWS 4
#define NBLK 256
#define RT 512
#define PT 320

// device scratch
__device__ float g_hidden[(size_t)TT * BB * HH];   // [t][b][j]  210 MB
__device__ float g_gi[(size_t)TT * BB * H3];       // [t][b][c]  630 MB (r/z biases folded)

typedef unsigned long long u64;

__device__ __forceinline__ u64 splat2(float w) {
    u64 r; asm("mov.b64 %0, {%1, %1};" : "=l"(r) : "f"(w)); return r;
}
__device__ __forceinline__ u64 pack2(float lo, float hi) {
    u64 r; asm("mov.b64 %0, {%1, %2};" : "=l"(r) : "f"(lo), "f"(hi)); return r;
}
__device__ __forceinline__ u64 fma2(u64 a, u64 b, u64 c) {
    u64 d; asm("fma.rn.f32x2 %0, %1, %2, %3;" : "=l"(d) : "l"(a), "l"(b), "l"(c)); return d;
}
__device__ __forceinline__ u64 add2(u64 a, u64 b) {
    u64 d; asm("add.rn.f32x2 %0, %1, %2;" : "=l"(d) : "l"(a), "l"(b)); return d;
}
__device__ __forceinline__ void unpk(u64 v, float& lo, float& hi) {
    asm("mov.b64 {%0, %1}, %2;" : "=f"(lo), "=f"(hi) : "l"(v));
}
__device__ __forceinline__ u64 shfl_bfly_u64(u64 v, int m) {
    unsigned lo, hi;
    asm("mov.b64 {%0, %1}, %2;" : "=r"(lo), "=r"(hi) : "l"(v));
    lo = __shfl_xor_sync(0xffffffffu, lo, m);
    hi = __shfl_xor_sync(0xffffffffu, hi, m);
    u64 r; asm("mov.b64 %0, {%1, %2};" : "=l"(r) : "r"(lo), "r"(hi));
    return r;
}
__device__ __forceinline__ float tanh_fast(float x) {
    float y; asm("tanh.approx.f32 %0, %1;" : "=f"(y) : "f"(x)); return y;
}
__device__ __forceinline__ float sigmoid_f(float x) {
    return 1.0f / (1.0f + __expf(-x));
}

// ============================================================
// Pre-kernel v4 (unchanged from R13 best): gi = x@W_ih^T + biases.
// ============================================================
#define PRE_XS_STRIDE 36
#define PRE_XS_FLOATS (64 * PRE_XS_STRIDE)
#define PRE_SMEM_FLOATS (19200 + 304 + 2 * PRE_XS_FLOATS)
__global__ void __launch_bounds__(PT, 2)
gi_precompute_kernel(const float* __restrict__ x,
                     const int*   __restrict__ lengths,
                     const float* __restrict__ W_ih,
                     const float* __restrict__ b_ih,
                     const float* __restrict__ b_hh) {
    extern __shared__ float sm[];
    __shared__ int s_npass;
    float* Wih_s = sm;
    float* bs    = sm + 19200;
    float* xs    = sm + 19504;

    const int tid = threadIdx.x;
    const int t = blockIdx.x >> 1;
    const int rbase = (blockIdx.x & 1) * 512;

    if (tid == 0) {
        int lo = 0, hi = BB;
        while (lo < hi) {
            int m = (lo + hi) >> 1;
            if (lengths[m] > t) lo = m + 1; else hi = m;
        }
        int na = lo - rbase;
        na = na < 0 ? 0 : (na > 512 ? 512 : na);
        s_npass = (na + 31) >> 5;
    }
    __syncthreads();
    const int npass = s_npass;
    if (npass == 0) return;

    for (int e = tid; e < H3 * VV; e += PT) {
        int c = e >> 6, v = e & 63;
        Wih_s[v * H3 + c] = W_ih[e];
    }
    for (int c = tid; c < H3; c += PT)
        bs[c] = b_ih[c] + ((c < 200) ? b_hh[c] : 0.0f);

    const size_t xrow0 = (size_t)t * BB + rbase;
    for (int e = tid; e < 1024; e += PT) {
        int rp = e >> 6, v = e & 63;
        float lo = x[(xrow0 + 2 * rp) * VV + v];
        float hi = x[(xrow0 + 2 * rp + 1) * VV + v];
        *(u64*)(xs + v * PRE_XS_STRIDE + rp * 2) = pack2(lo, hi);
    }
    __syncthreads();

    const int rq = tid / 80;
    const int cg = tid - rq * 80;
    const bool act = (cg < 75);
    const int c0 = cg * 4;
    float4 bq = make_float4(0.f, 0.f, 0.f, 0.f);
    if (act) bq = *(const float4*)(bs + c0);

    for (int pass = 0; pass < npass; pass++) {
        const int buf = pass & 1;
        const bool has = (pass + 1 < npass);
        u64 pf[4];
        if (has) {
            const size_t base = (xrow0 + (pass + 1) * 32) * VV;
#pragma unroll
            for (int i = 0; i < 4; i++) {
                int e = tid + i * PT;
                if (e < 1024) {
                    int rp = e >> 6, v = e & 63;
                    float lo = x[base + (size_t)(2 * rp) * VV + v];
                    float hi = x[base + (size_t)(2 * rp + 1) * VV + v];
                    pf[i] = pack2(lo, hi);
                }
            }
        }
        if (act) {
            u64 a0[4], a1[4], a2[4], a3[4];
#pragma unroll
            for (int i = 0; i < 4; i++) { a0[i] = 0; a1[i] = 0; a2[i] = 0; a3[i] = 0; }
            const float* wv = Wih_s + c0;
            const float* xb = xs + buf * PRE_XS_FLOATS + rq * 8;
#pragma unroll 4
            for (int v = 0; v < VV; v++) {
                float4 w4 = *(const float4*)(wv + v * H3);
                u64 w0 = splat2(w4.x);
                u64 w1 = splat2(w4.y);
                u64 w2 = splat2(w4.z);
                u64 w3 = splat2(w4.w);
                ulonglong2 p = *(const ulonglong2*)(xb + v * PRE_XS_STRIDE);
                ulonglong2 q = *(const ulonglong2*)(xb + v * PRE_XS_STRIDE + 4);
                a0[0] = fma2(w0, p.x, a0[0]); a0[1] = fma2(w0, p.y, a0[1]);
                a0[2] = fma2(w0, q.x, a0[2]); a0[3] = fma2(w0, q.y, a0[3]);
                a1[0] = fma2(w1, p.x, a1[0]); a1[1] = fma2(w1, p.y, a1[1]);
                a1[2] = fma2(w1, q.x, a1[2]); a1[3] = fma2(w1, q.y, a1[3]);
                a2[0] = fma2(w2, p.x, a2[0]); a2[1] = fma2(w2, p.y, a2[1]);
                a2[2] = fma2(w2, q.x, a2[2]); a2[3] = fma2(w2, q.y, a2[3]);
                a3[0] = fma2(w3, p.x, a3[0]); a3[1] = fma2(w3, p.y, a3[1]);
                a3[2] = fma2(w3, q.x, a3[2]); a3[3] = fma2(w3, q.y, a3[3]);
            }
            const size_t rowbase = xrow0 + pass * 32 + rq * 8;
#pragma unroll
            for (int rp = 0; rp < 4; rp++) {
                float f00, f01, f10, f11, f20, f21, f30, f31;
                unpk(a0[rp], f00, f01);
                unpk(a1[rp], f10, f11);
                unpk(a2[rp], f20, f21);
                unpk(a3[rp], f30, f31);
                float4 o0 = make_float4(f00 + bq.x, f10 + bq.y, f20 + bq.z, f30 + bq.w);
                float4 o1 = make_float4(f01 + bq.x, f11 + bq.y, f21 + bq.z, f31 + bq.w);
                *(float4*)&g_gi[(rowbase + 2 * rp) * H3 + c0]     = o0;
                *(float4*)&g_gi[(rowbase + 2 * rp + 1) * H3 + c0] = o1;
            }
        }
        if (has) {
            float* xd = xs + (buf ^ 1) * PRE_XS_FLOATS;
#pragma unroll
            for (int i = 0; i < 4; i++) {
                int e = tid + i * PT;
                if (e < 1024) {
                    int rp = e >> 6, v = e & 63;
                    *(u64*)(xd + v * PRE_XS_STRIDE + rp * 2) = pf[i];
                }
            }
        }
        __syncthreads();
    }
}

// ============================================================
// Recurrent kernel v2 (FIXED): single-phase, shfl-reduced, one barrier/step.
// 256 blocks x 4 rows, 512 threads: (j = tid>>2, kq = tid&3).
// ALL threads run the dot + butterfly (no divergent shuffles);
// only gate math + stores guarded by act.
// ============================================================
#define OFF_HS 0                  // [100][4] hs[k*4+r]
#define OFF_GI 400                // [2][4][300] gi_s[buf*1200 + r*300 + c]
#define OFF_LEN 2800              // 4 ints
#define REC_SMEM_FLOATS (OFF_LEN + 4)
#define REC_SMEM_BYTES (REC_SMEM_FLOATS * 4)

__global__ void __launch_bounds__(RT, 1)
gru_recurrent_kernel(const float* __restrict__ h0,
                     const int*   __restrict__ lengths,
                     const float* __restrict__ W_hh,
                     const float* __restrict__ b_hh) {
    extern __shared__ float sm[];
    int* len_s = (int*)(sm + OFF_LEN);
    const int tid = threadIdx.x;
    const int row0 = blockIdx.x * ROWS;

    const int j  = tid >> 2;
    const int kq = tid & 3;
    const bool act = (j < HH);
    const int jc = act ? j : 0;          // clamped j for safe loads
    const int kbase = kq * 25;

    if (tid < ROWS) len_s[tid] = lengths[row0 + tid];

    // weights: 3 gate rows for jc, k-range kbase..+25 (all threads load)
    float wR[25], wZ[25], wN[25];
    {
        const float* pR = W_hh + jc * 100 + kbase;
        const float* pZ = W_hh + (jc + 100) * 100 + kbase;
        const float* pN = W_hh + (jc + 200) * 100 + kbase;
#pragma unroll
        for (int i = 0; i < 25; i++) { wR[i] = pR[i]; wZ[i] = pZ[i]; wN[i] = pN[i]; }
    }
    const float bhn = b_hh[200 + jc];
    float hold = h0[(size_t)(row0 + kq) * HH + jc];
    if (act) sm[OFF_HS + tid] = hold;    // hs[j*4 + kq]

    // prefetch gi tile for t=0 (1200 floats)
    if (tid < 300) {
        unsigned int sa = (unsigned int)__cvta_generic_to_shared(sm + OFF_GI + tid * 4);
        const float* gp = g_gi + ((size_t)0 * BB + row0) * H3 + tid * 4;
        asm volatile("cp.async.ca.shared.global [%0], [%1], 16;" :: "r"(sa), "l"(gp));
    }
    asm volatile("cp.async.commit_group;");
    __syncthreads();

    int ml = len_s[0];
#pragma unroll
    for (int i = 1; i < ROWS; i++) ml = max(ml, len_s[i]);
    const int mylen = len_s[kq];

    for (int t = 0; t < ml; t++) {
        const int buf = t & 1;
        const int nbuf = buf ^ 1;

        // prefetch gi for t+1
        {
            int tp = (t + 1 < ml) ? (t + 1) : t;
            if (tid < 300) {
                unsigned int sa = (unsigned int)__cvta_generic_to_shared(
                    sm + OFF_GI + nbuf * 1200 + tid * 4);
                const float* gp = g_gi + ((size_t)tp * BB + row0) * H3 + tid * 4;
                asm volatile("cp.async.ca.shared.global [%0], [%1], 16;" :: "r"(sa), "l"(gp));
            }
            asm volatile("cp.async.commit_group;");
        }

        // ---- partial dots over 25 k, rows packed (01)(23) — ALL threads ----
        const float* hsb = sm + OFF_HS + kbase * 4;
        u64 aR[2] = {0, 0}, aZ[2] = {0, 0}, aN[2] = {0, 0};
#pragma unroll
        for (int i = 0; i < 25; i++) {
            ulonglong2 hp = *(const ulonglong2*)(hsb + i * 4);   // rows 0-3
            u64 wr = splat2(wR[i]);
            u64 wz = splat2(wZ[i]);
            u64 wn = splat2(wN[i]);
            aR[0] = fma2(wr, hp.x, aR[0]); aR[1] = fma2(wr, hp.y, aR[1]);
            aZ[0] = fma2(wz, hp.x, aZ[0]); aZ[1] = fma2(wz, hp.y, aZ[1]);
            aN[0] = fma2(wn, hp.x, aN[0]); aN[1] = fma2(wn, hp.y, aN[1]);
        }
        // ---- butterfly reduce over kq lanes (xor 1, 2) — ALL threads ----
#pragma unroll
        for (int m = 1; m <= 2; m <<= 1) {
            aR[0] = add2(aR[0], shfl_bfly_u64(aR[0], m));
            aR[1] = add2(aR[1], shfl_bfly_u64(aR[1], m));
            aZ[0] = add2(aZ[0], shfl_bfly_u64(aZ[0], m));
            aZ[1] = add2(aZ[1], shfl_bfly_u64(aZ[1], m));
            aN[0] = add2(aN[0], shfl_bfly_u64(aN[0], m));
            aN[1] = add2(aN[1], shfl_bfly_u64(aN[1], m));
        }
        asm volatile("cp.async.wait_group 1;");

        if (act) {
            // lane kq takes row r = kq
            float lo, hi;
            float s_r, s_z, s_n;
            unpk((kq & 2) ? aR[1] : aR[0], lo, hi); s_r = (kq & 1) ? hi : lo;
            unpk((kq & 2) ? aZ[1] : aZ[0], lo, hi); s_z = (kq & 1) ? hi : lo;
            unpk((kq & 2) ? aN[1] : aN[0], lo, hi); s_n = (kq & 1) ? hi : lo;

            const float* gs = sm + OFF_GI + buf * 1200 + kq * H3 + j;
            float rg = sigmoid_f(gs[0] + s_r);
            float zg = sigmoid_f(gs[100] + s_z);
            float nv = tanh_fast(fmaf(rg, s_n + bhn, gs[200]));
            float hnew = fmaf(zg, hold - nv, nv);
            float hout = (t < mylen) ? hnew : hold;
            hold = hout;
            sm[OFF_HS + tid] = hout;                      // coalesced STS.32
            g_hidden[((size_t)t * BB + row0 + kq) * HH + j] = hout;
        }
        __syncthreads();
    }
}

// ============================================================
// Epilogue: software-pipelined, unchanged from R9 (best).
// ============================================================
struct QS {
    float h[4][4];
    bool act[4];
    bool any;
};

__device__ __forceinline__ void loadq(QS& s, int q, int lane,
                                      const int* __restrict__ lengths) {
    int rid0 = q * 4;
    int t  = q >> 8;
    int b0 = rid0 & 1023;
    int L0 = lengths[b0];
    s.any = (t < L0);
    if (!s.any) return;
    s.act[0] = true;
    s.act[1] = t < lengths[b0 + 1];
    s.act[2] = t < lengths[b0 + 2];
    s.act[3] = t < lengths[b0 + 3];
#pragma unroll
    for (int i = 0; i < 4; i++) {
        const float* hp = g_hidden + (size_t)(rid0 + i) * HH;
        s.h[i][0] = hp[lane];
        s.h[i][1] = hp[lane + 32];
        s.h[i][2] = hp[lane + 64];
        s.h[i][3] = (lane < 4) ? hp[lane + 96] : 0.0f;
    }
}

__device__ __forceinline__ void procq(const QS& s, int q, int w, int lane,
                                      const float* Wo, float bo0, float bo1,
                                      float (*hq)[HH * 4],
                                      float* __restrict__ out) {
    int rid0 = q * 4;
    float* op = out + (size_t)rid0 * VV;
#pragma unroll
    for (int i = 0; i < 4; i++) {
        hq[w][lane * 4 + i]        = s.h[i][0];
        hq[w][(lane + 32) * 4 + i] = s.h[i][1];
        hq[w][(lane + 64) * 4 + i] = s.h[i][2];
        if (lane < 4) hq[w][(lane + 96) * 4 + i] = s.h[i][3];
    }
    __syncwarp();
    float acc0[4] = {0.f, 0.f, 0.f, 0.f};
    float acc1[4] = {0.f, 0.f, 0.f, 0.f};
#pragma unroll 5
    for (int k = 0; k < HH; k++) {
        float4 hv = *(const float4*)&hq[w][k * 4];
        float w0 = Wo[k * VV + lane];
        float w1 = Wo[k * VV + lane + 32];
        acc0[0] = fmaf(hv.x, w0, acc0[0]); acc1[0] = fmaf(hv.x, w1, acc1[0]);
        acc0[1] = fmaf(hv.y, w0, acc0[1]); acc1[1] = fmaf(hv.y, w1, acc1[1]);
        acc0[2] = fmaf(hv.z, w0, acc0[2]); acc1[2] = fmaf(hv.z, w1, acc1[2]);
        acc0[3] = fmaf(hv.w, w0, acc0[3]); acc1[3] = fmaf(hv.w, w1, acc1[3]);
    }
#pragma unroll
    for (int i = 0; i < 4; i++) {
        if (!s.act[i]) continue;
        float l0 = acc0[i] + bo0;
        float l1 = acc1[i] + bo1;
        float m = fmaxf(l0, l1);
#pragma unroll
        for (int sh = 16; sh; sh >>= 1) m = fmaxf(m, __shfl_xor_sync(0xffffffffu, m, sh));
        float se = __expf(l0 - m) + __expf(l1 - m);
#pragma unroll
        for (int sh = 16; sh; sh >>= 1) se += __shfl_xor_sync(0xffffffffu, se, sh);
        float lse = m + __logf(se);
        op[i * VV + lane]      = l0 - lse;
        op[i * VV + lane + 32] = l1 - lse;
    }
    __syncwarp();
}

__global__ void __launch_bounds__(256)
gru_output_kernel(const int*   __restrict__ lengths,
                  const float* __restrict__ W_out,
                  const float* __restrict__ b_out,
                  float*       __restrict__ out) {
    __shared__ float Wo[HH * VV];
    __shared__ float bo[VV];
    __shared__ float hq[8][HH * 4];
    const int tid = threadIdx.x;
    for (int e = tid; e < VV * HH; e += 256) {
        int cc = e / 100, k = e - cc * 100;
        Wo[k * VV + cc] = W_out[e];
    }
    if (tid < VV) bo[tid] = b_out[tid];
    __syncthreads();

    const int w = tid >> 5;
    const int lane = tid & 31;
    const float bo0 = bo[lane];
    const float bo1 = bo[lane + 32];
    const int nquad = (TT * BB) / 4;
    const int stride = gridDim.x * 8;

    QS A, B;
    int q = blockIdx.x * 8 + w;
    if (q < nquad) loadq(A, q, lane, lengths);
    while (q < nquad) {
        int qn = q + stride;
        if (qn < nquad) loadq(B, qn, lane, lengths);
        if (A.any) procq(A, q, w, lane, Wo, bo0, bo1, hq, out);
        q = qn;
        if (q >= nquad) break;
        qn = q + stride;
        if (qn < nquad) loadq(A, qn, lane, lengths);
        if (B.any) procq(B, q, w, lane, Wo, bo0, bo1, hq, out);
        q = qn;
    }
}

extern "C" void kernel_launch(void* const* d_in, const int* in_sizes, int n_in,
                              void* d_out, int out_size) {
    const float* x      = (const float*)d_in[0];
    const float* h0     = (const float*)d_in[1];
    const int*   lens   = (const int*)  d_in[2];
    const float* W_ih   = (const float*)d_in[3];
    const float* W_hh   = (const float*)d_in[4];
    const float* b_ih   = (const float*)d_in[5];
    const float* b_hh   = (const float*)d_in[6];
    const float* W_out  = (const float*)d_in[7];
    const float* b_out  = (const float*)d_in[8];
    float* out = (float*)d_out;

    cudaFuncSetAttribute(gi_precompute_kernel,
                         cudaFuncAttributeMaxDynamicSharedMemorySize, PRE_SMEM_FLOATS * 4);
    cudaFuncSetAttribute(gru_recurrent_kernel,
                         cudaFuncAttributeMaxDynamicSharedMemorySize, REC_SMEM_BYTES);

    cudaMemsetAsync(out, 0, (size_t)out_size * sizeof(float));
    gi_precompute_kernel<<<2 * TT, PT, PRE_SMEM_FLOATS * 4>>>(x, lens, W_ih, b_ih, b_hh);
    gru_recurrent_kernel<<<NBLK, RT, REC_SMEM_BYTES>>>(h0, lens, W_hh, b_hh);
    gru_output_kernel<<<2048, 256>>>(lens, W_out, b_out, out);
}

// round 16
// speedup vs baseline: 1.1539x; 1.1539x over previous
#include <cuda_runtime.h>
#include <cstdint>

#define TT 512
#define BB 1024
#define VV 64
#define HH 100
#define H3 300
#define ROWS 4
#define NBLK 256
#define RT 640
#define PT 320

// device scratch
__device__ float g_hidden[(size_t)TT * BB * HH];   // [t][b][j]  210 MB
__device__ float g_gi[(size_t)TT * BB * H3];       // [t][b][c]  630 MB (biases folded)

typedef unsigned long long u64;

__device__ __forceinline__ u64 splat2(float w) {
    u64 r; asm("mov.b64 %0, {%1, %1};" : "=l"(r) : "f"(w)); return r;
}
__device__ __forceinline__ u64 pack2(float lo, float hi) {
    u64 r; asm("mov.b64 %0, {%1, %2};" : "=l"(r) : "f"(lo), "f"(hi)); return r;
}
__device__ __forceinline__ u64 fma2(u64 a, u64 b, u64 c) {
    u64 d; asm("fma.rn.f32x2 %0, %1, %2, %3;" : "=l"(d) : "l"(a), "l"(b), "l"(c)); return d;
}
__device__ __forceinline__ void unpk(u64 v, float& lo, float& hi) {
    asm("mov.b64 {%0, %1}, %2;" : "=f"(lo), "=f"(hi) : "l"(v));
}
__device__ __forceinline__ float tanh_fast(float x) {
    float y; asm("tanh.approx.f32 %0, %1;" : "=f"(y) : "f"(x)); return y;
}
__device__ __forceinline__ float sigmoid_t(float x) {
    return fmaf(0.5f, tanh_fast(0.5f * x), 0.5f);
}

// ============================================================
// Pre-kernel v4 (R13 best): gi = x@W_ih^T + biases, 4col x 8row tile.
// ============================================================
#define PRE_XS_STRIDE 36
#define PRE_XS_FLOATS (64 * PRE_XS_STRIDE)
#define PRE_SMEM_FLOATS (19200 + 304 + 2 * PRE_XS_FLOATS)
__global__ void __launch_bounds__(PT, 2)
gi_precompute_kernel(const float* __restrict__ x,
                     const int*   __restrict__ lengths,
                     const float* __restrict__ W_ih,
                     const float* __restrict__ b_ih,
                     const float* __restrict__ b_hh) {
    extern __shared__ float sm[];
    __shared__ int s_npass;
    float* Wih_s = sm;
    float* bs    = sm + 19200;
    float* xs    = sm + 19504;

    const int tid = threadIdx.x;
    const int t = blockIdx.x >> 1;
    const int rbase = (blockIdx.x & 1) * 512;

    if (tid == 0) {
        int lo = 0, hi = BB;
        while (lo < hi) {
            int m = (lo + hi) >> 1;
            if (lengths[m] > t) lo = m + 1; else hi = m;
        }
        int na = lo - rbase;
        na = na < 0 ? 0 : (na > 512 ? 512 : na);
        s_npass = (na + 31) >> 5;
    }
    __syncthreads();
    const int npass = s_npass;
    if (npass == 0) return;

    for (int e = tid; e < H3 * VV; e += PT) {
        int c = e >> 6, v = e & 63;
        Wih_s[v * H3 + c] = W_ih[e];
    }
    for (int c = tid; c < H3; c += PT)
        bs[c] = b_ih[c] + ((c < 200) ? b_hh[c] : 0.0f);

    const size_t xrow0 = (size_t)t * BB + rbase;
    for (int e = tid; e < 1024; e += PT) {
        int rp = e >> 6, v = e & 63;
        float lo = x[(xrow0 + 2 * rp) * VV + v];
        float hi = x[(xrow0 + 2 * rp + 1) * VV + v];
        *(u64*)(xs + v * PRE_XS_STRIDE + rp * 2) = pack2(lo, hi);
    }
    __syncthreads();

    const int rq = tid / 80;
    const int cg = tid - rq * 80;
    const bool act = (cg < 75);
    const int c0 = cg * 4;
    float4 bq = make_float4(0.f, 0.f, 0.f, 0.f);
    if (act) bq = *(const float4*)(bs + c0);

    for (int pass = 0; pass < npass; pass++) {
        const int buf = pass & 1;
        const bool has = (pass + 1 < npass);
        u64 pf[4];
        if (has) {
            const size_t base = (xrow0 + (pass + 1) * 32) * VV;
#pragma unroll
            for (int i = 0; i < 4; i++) {
                int e = tid + i * PT;
                if (e < 1024) {
                    int rp = e >> 6, v = e & 63;
                    float lo = x[base + (size_t)(2 * rp) * VV + v];
                    float hi = x[base + (size_t)(2 * rp + 1) * VV + v];
                    pf[i] = pack2(lo, hi);
                }
            }
        }
        if (act) {
            u64 a0[4], a1[4], a2[4], a3[4];
#pragma unroll
            for (int i = 0; i < 4; i++) { a0[i] = 0; a1[i] = 0; a2[i] = 0; a3[i] = 0; }
            const float* wv = Wih_s + c0;
            const float* xb = xs + buf * PRE_XS_FLOATS + rq * 8;
#pragma unroll 4
            for (int v = 0; v < VV; v++) {
                float4 w4 = *(const float4*)(wv + v * H3);
                u64 w0 = splat2(w4.x);
                u64 w1 = splat2(w4.y);
                u64 w2 = splat2(w4.z);
                u64 w3 = splat2(w4.w);
                ulonglong2 p = *(const ulonglong2*)(xb + v * PRE_XS_STRIDE);
                ulonglong2 q = *(const ulonglong2*)(xb + v * PRE_XS_STRIDE + 4);
                a0[0] = fma2(w0, p.x, a0[0]); a0[1] = fma2(w0, p.y, a0[1]);
                a0[2] = fma2(w0, q.x, a0[2]); a0[3] = fma2(w0, q.y, a0[3]);
                a1[0] = fma2(w1, p.x, a1[0]); a1[1] = fma2(w1, p.y, a1[1]);
                a1[2] = fma2(w1, q.x, a1[2]); a1[3] = fma2(w1, q.y, a1[3]);
                a2[0] = fma2(w2, p.x, a2[0]); a2[1] = fma2(w2, p.y, a2[1]);
                a2[2] = fma2(w2, q.x, a2[2]); a2[3] = fma2(w2, q.y, a2[3]);
                a3[0] = fma2(w3, p.x, a3[0]); a3[1] = fma2(w3, p.y, a3[1]);
                a3[2] = fma2(w3, q.x, a3[2]); a3[3] = fma2(w3, q.y, a3[3]);
            }
            const size_t rowbase = xrow0 + pass * 32 + rq * 8;
#pragma unroll
            for (int rp = 0; rp < 4; rp++) {
                float f00, f01, f10, f11, f20, f21, f30, f31;
                unpk(a0[rp], f00, f01);
                unpk(a1[rp], f10, f11);
                unpk(a2[rp], f20, f21);
                unpk(a3[rp], f30, f31);
                float4 o0 = make_float4(f00 + bq.x, f10 + bq.y, f20 + bq.z, f30 + bq.w);
                float4 o1 = make_float4(f01 + bq.x, f11 + bq.y, f21 + bq.z, f31 + bq.w);
                *(float4*)&g_gi[(rowbase + 2 * rp) * H3 + c0]     = o0;
                *(float4*)&g_gi[(rowbase + 2 * rp + 1) * H3 + c0] = o1;
            }
        }
        if (has) {
            float* xd = xs + (buf ^ 1) * PRE_XS_FLOATS;
#pragma unroll
            for (int i = 0; i < 4; i++) {
                int e = tid + i * PT;
                if (e < 1024) {
                    int rp = e >> 6, v = e & 63;
                    *(u64*)(xd + v * PRE_XS_STRIDE + rp * 2) = pf[i];
                }
            }
        }
        __syncthreads();
    }
}

// ============================================================
// Recurrent kernel: R9/R13 two-phase (best), sigmoid via MUFU.TANH.
// ============================================================
#define OFF_HS 0
#define OFF_H2 400
#define OFF_PG 800
#define OFF_GI 5600
#define OFF_BHN 8000
#define OFF_LEN 8100
#define REC_SMEM_FLOATS (OFF_LEN + 4)
#define REC_SMEM_BYTES (REC_SMEM_FLOATS * 4)

__global__ void __launch_bounds__(RT, 1)
gru_recurrent_kernel(const float* __restrict__ h0,
                     const int*   __restrict__ lengths,
                     const float* __restrict__ W_hh,
                     const float* __restrict__ b_hh) {
    extern __shared__ float sm[];
    int* len_s = (int*)(sm + OFF_LEN);
    const int tid = threadIdx.x;
    const int row0 = blockIdx.x * ROWS;

    if (tid < 100) sm[OFF_BHN + tid] = b_hh[200 + tid];
    for (int e = tid; e < ROWS * HH; e += RT) {
        int r = e / 100, j = e - r * 100;
        float hv = h0[(size_t)(row0 + r) * HH + j];
        sm[OFF_HS + j * ROWS + r] = hv;
        sm[OFF_H2 + r * HH + j]   = hv;
    }
    if (tid < ROWS) len_s[tid] = lengths[row0 + tid];

    const int kq = tid / 160;
    const int cp = tid - kq * 160;
    const bool act = (cp < 150);
    const int kbase = kq * 25;

    float wA[25], wB[25];
    if (act) {
        const float* pA = W_hh + cp * 100 + kbase;
        const float* pB = W_hh + (cp + 150) * 100 + kbase;
#pragma unroll
        for (int i = 0; i < 25; i++) { wA[i] = pA[i]; wB[i] = pB[i]; }
    }

    if (tid < 300) {
        unsigned int sa = (unsigned int)__cvta_generic_to_shared(sm + OFF_GI + tid * 4);
        const float* gp = g_gi + ((size_t)0 * BB + row0) * H3 + tid * 4;
        asm volatile("cp.async.ca.shared.global [%0], [%1], 16;" :: "r"(sa), "l"(gp));
    }
    asm volatile("cp.async.commit_group;");
    __syncthreads();

    int ml = len_s[0];
#pragma unroll
    for (int i = 1; i < ROWS; i++) ml = max(ml, len_s[i]);

    for (int t = 0; t < ml; t++) {
        const int buf = t & 1;
        const int nbuf = buf ^ 1;

        if (act) {
            const float* hsb = sm + OFF_HS + kbase * ROWS;
            u64 a0[2], a1[2];
            a0[0] = 0; a0[1] = 0; a1[0] = 0; a1[1] = 0;
#pragma unroll
            for (int i = 0; i < 25; i++) {
                u64 w0 = splat2(wA[i]);
                u64 w1 = splat2(wB[i]);
                ulonglong2 p = *(const ulonglong2*)(hsb + i * ROWS);
                a0[0] = fma2(w0, p.x, a0[0]); a0[1] = fma2(w0, p.y, a0[1]);
                a1[0] = fma2(w1, p.x, a1[0]); a1[1] = fma2(w1, p.y, a1[1]);
            }
            float* pgk = sm + OFF_PG + kq * 1200 + cp;
            float f0, f1;
            unpk(a0[0], f0, f1); pgk[0 * H3] = f0; pgk[1 * H3] = f1;
            unpk(a0[1], f0, f1); pgk[2 * H3] = f0; pgk[3 * H3] = f1;
            float* pgk2 = pgk + 150;
            unpk(a1[0], f0, f1); pgk2[0 * H3] = f0; pgk2[1 * H3] = f1;
            unpk(a1[1], f0, f1); pgk2[2 * H3] = f0; pgk2[3 * H3] = f1;
        }

        {
            int tp = (t + 1 < ml) ? (t + 1) : t;
            if (tid < 300) {
                unsigned int sa = (unsigned int)__cvta_generic_to_shared(
                    sm + OFF_GI + nbuf * 1200 + tid * 4);
                const float* gp = g_gi + ((size_t)tp * BB + row0) * H3 + tid * 4;
                asm volatile("cp.async.ca.shared.global [%0], [%1], 16;" :: "r"(sa), "l"(gp));
            }
            asm volatile("cp.async.commit_group;");
        }
        asm volatile("cp.async.wait_group 1;");
        __syncthreads();

        if (tid < ROWS * HH) {
            int o = tid;
            int r = o / 100;
            int j = o - r * 100;
            const float* pgr = sm + OFF_PG + r * H3 + j;
            float s_r = pgr[0]   + pgr[1200]       + pgr[2400]       + pgr[3600];
            float s_z = pgr[100] + pgr[1200 + 100] + pgr[2400 + 100] + pgr[3600 + 100];
            float s_n = pgr[200] + pgr[1200 + 200] + pgr[2400 + 200] + pgr[3600 + 200];
            const float* gs = sm + OFF_GI + buf * 1200 + r * H3 + j;
            float rg = sigmoid_t(gs[0] + s_r);
            float zg = sigmoid_t(gs[100] + s_z);
            float hn = s_n + sm[OFF_BHN + j];
            float nv = tanh_fast(fmaf(rg, hn, gs[200]));
            float hold = sm[OFF_H2 + r * HH + j];
            float hnew = fmaf(zg, hold - nv, nv);
            float hout = (t < len_s[r]) ? hnew : hold;
            sm[OFF_H2 + r * HH + j] = hout;
            sm[OFF_HS + j * ROWS + r] = hout;
            g_hidden[((size_t)t * BB + row0 + r) * HH + j] = hout;
        }
        __syncthreads();
    }
}

// ============================================================
// Epilogue v3: 8 rows/warp, pipelined; d_out pre-zeroed by memset.
// ============================================================
struct OS {
    float h[8][4];
    bool act[8];
    bool any;
};

__device__ __forceinline__ void loado(OS& s, int o, int lane,
                                      const int* __restrict__ lengths) {
    int rid0 = o * 8;
    int t  = o >> 7;               // rid0 >> 10
    int b0 = rid0 & 1023;
    s.any = (t < lengths[b0]);     // sorted desc -> first row gates the octet
    if (!s.any) return;
#pragma unroll
    for (int i = 0; i < 8; i++) s.act[i] = (t < lengths[b0 + i]);
#pragma unroll
    for (int i = 0; i < 8; i++) {
        const float* hp = g_hidden + (size_t)(rid0 + i) * HH;
        s.h[i][0] = hp[lane];
        s.h[i][1] = hp[lane + 32];
        s.h[i][2] = hp[lane + 64];
        s.h[i][3] = (lane < 4) ? hp[lane + 96] : 0.0f;
    }
}

__device__ __forceinline__ void proco(const OS& s, int o, int w, int lane,
                                      const float* Wo, float bo0, float bo1,
                                      float (*hq)[HH * 8],
                                      float* __restrict__ out) {
    int rid0 = o * 8;
    float* op = out + (size_t)rid0 * VV;
#pragma unroll
    for (int i = 0; i < 8; i++) {
        hq[w][lane * 8 + i]        = s.h[i][0];
        hq[w][(lane + 32) * 8 + i] = s.h[i][1];
        hq[w][(lane + 64) * 8 + i] = s.h[i][2];
        if (lane < 4) hq[w][(lane + 96) * 8 + i] = s.h[i][3];
    }
    __syncwarp();
    float acc0[8] = {0.f, 0.f, 0.f, 0.f, 0.f, 0.f, 0.f, 0.f};
    float acc1[8] = {0.f, 0.f, 0.f, 0.f, 0.f, 0.f, 0.f, 0.f};
#pragma unroll 4
    for (int k = 0; k < HH; k++) {
        float4 ha = *(const float4*)&hq[w][k * 8];
        float4 hb = *(const float4*)&hq[w][k * 8 + 4];
        float w0 = Wo[k * VV + lane];
        float w1 = Wo[k * VV + lane + 32];
        acc0[0] = fmaf(ha.x, w0, acc0[0]); acc1[0] = fmaf(ha.x, w1, acc1[0]);
        acc0[1] = fmaf(ha.y, w0, acc0[1]); acc1[1] = fmaf(ha.y, w1, acc1[1]);
        acc0[2] = fmaf(ha.z, w0, acc0[2]); acc1[2] = fmaf(ha.z, w1, acc1[2]);
        acc0[3] = fmaf(ha.w, w0, acc0[3]); acc1[3] = fmaf(ha.w, w1, acc1[3]);
        acc0[4] = fmaf(hb.x, w0, acc0[4]); acc1[4] = fmaf(hb.x, w1, acc1[4]);
        acc0[5] = fmaf(hb.y, w0, acc0[5]); acc1[5] = fmaf(hb.y, w1, acc1[5]);
        acc0[6] = fmaf(hb.z, w0, acc0[6]); acc1[6] = fmaf(hb.z, w1, acc1[6]);
        acc0[7] = fmaf(hb.w, w0, acc0[7]); acc1[7] = fmaf(hb.w, w1, acc1[7]);
    }
#pragma unroll
    for (int i = 0; i < 8; i++) {
        if (!s.act[i]) continue;
        float l0 = acc0[i] + bo0;
        float l1 = acc1[i] + bo1;
        float m = fmaxf(l0, l1);
#pragma unroll
        for (int sh = 16; sh; sh >>= 1) m = fmaxf(m, __shfl_xor_sync(0xffffffffu, m, sh));
        float se = __expf(l0 - m) + __expf(l1 - m);
#pragma unroll
        for (int sh = 16; sh; sh >>= 1) se += __shfl_xor_sync(0xffffffffu, se, sh);
        float lse = m + __logf(se);
        op[i * VV + lane]      = l0 - lse;
        op[i * VV + lane + 32] = l1 - lse;
    }
    __syncwarp();
}

__global__ void __launch_bounds__(256, 2)
gru_output_kernel(const int*   __restrict__ lengths,
                  const float* __restrict__ W_out,
                  const float* __restrict__ b_out,
                  float*       __restrict__ out) {
    __shared__ float Wo[HH * VV];
    __shared__ float bo[VV];
    __shared__ float hq[8][HH * 8];
    const int tid = threadIdx.x;
    for (int e = tid; e < VV * HH; e += 256) {
        int cc = e / 100, k = e - cc * 100;
        Wo[k * VV + cc] = W_out[e];
    }
    if (tid < VV) bo[tid] = b_out[tid];
    __syncthreads();

    const int w = tid >> 5;
    const int lane = tid & 31;
    const float bo0 = bo[lane];
    const float bo1 = bo[lane + 32];
    const int noct = (TT * BB) / 8;      // 65536
    const int stride = gridDim.x * 8;

    OS A, B;
    int o = blockIdx.x * 8 + w;
    if (o < noct) loado(A, o, lane, lengths);
    while (o < noct) {
        int on = o + stride;
        if (on < noct) loado(B, on, lane, lengths);
        if (A.any) proco(A, o, w, lane, Wo, bo0, bo1, hq, out);
        o = on;
        if (o >= noct) break;
        on = o + stride;
        if (on < noct) loado(A, on, lane, lengths);
        if (B.any) proco(B, o, w, lane, Wo, bo0, bo1, hq, out);
        o = on;
    }
}

extern "C" void kernel_launch(void* const* d_in, const int* in_sizes, int n_in,
                              void* d_out, int out_size) {
    const float* x      = (const float*)d_in[0];
    const float* h0     = (const float*)d_in[1];
    const int*   lens   = (const int*)  d_in[2];
    const float* W_ih   = (const float*)d_in[3];
    const float* W_hh   = (const float*)d_in[4];
    const float* b_ih   = (const float*)d_in[5];
    const float* b_hh   = (const float*)d_in[6];
    const float* W_out  = (const float*)d_in[7];
    const float* b_out  = (const float*)d_in[8];
    float* out = (float*)d_out;

    cudaFuncSetAttribute(gi_precompute_kernel,
                         cudaFuncAttributeMaxDynamicSharedMemorySize, PRE_SMEM_FLOATS * 4);
    cudaFuncSetAttribute(gru_recurrent_kernel,
                         cudaFuncAttributeMaxDynamicSharedMemorySize, REC_SMEM_BYTES);

    cudaMemsetAsync(out, 0, (size_t)out_size * sizeof(float));
    gi_precompute_kernel<<<2 * TT, PT, PRE_SMEM_FLOATS * 4>>>(x, lens, W_ih, b_ih, b_hh);
    gru_recurrent_kernel<<<NBLK, RT, REC_SMEM_BYTES>>>(h0, lens, W_hh, b_hh);
    gru_output_kernel<<<2048, 256>>>(lens, W_out, b_out, out);
}